// round 3
// baseline (speedup 1.0000x reference)
#include <cuda_runtime.h>

// Problem-fixed maxima (N=100000 nodes, E=1600000 edges, IN=128, RANK=64, HID=128)
#define MAXN 100000
#define MAXE 1600000

// ---------------- scratch (static device globals; no allocation) ----------------
__device__ float g_h[MAXN * 64];      // h = x @ W
__device__ float g_tx[MAXN * 64];     // trans_x = norm * segment_prod
__device__ int   g_cnt[MAXN];         // in-degree histogram
__device__ int   g_off[MAXN + 1];     // CSR offsets (exclusive scan)
__device__ int   g_cur[MAXN];         // scatter cursors
__device__ int   g_bsum[256];         // per-block scan partials
__device__ int   g_ssrc[MAXE];        // src ids sorted by dst

// ---------------- packed fp32x2 helpers (Blackwell FFMA2) ----------------
__device__ __forceinline__ unsigned long long ffma2(unsigned long long a,
                                                    unsigned long long b,
                                                    unsigned long long c) {
    unsigned long long d;
    asm("fma.rn.f32x2 %0, %1, %2, %3;" : "=l"(d) : "l"(a), "l"(b), "l"(c));
    return d;
}
__device__ __forceinline__ unsigned long long dup2(float v) {
    unsigned long long r;
    asm("mov.b64 %0, {%1, %1};" : "=l"(r) : "f"(v));
    return r;
}

// ---------------- counting-sort machinery ----------------
__global__ void k_zero(int n) {
    int i = blockIdx.x * blockDim.x + threadIdx.x;
    if (i < n) g_cnt[i] = 0;
}

__global__ void k_hist(const int* __restrict__ dst, int e) {
    int i = blockIdx.x * blockDim.x + threadIdx.x;
    if (i < e) atomicAdd(&g_cnt[dst[i]], 1);
}

__global__ void k_scanA(int n) {  // 1024 threads/block, block-local exclusive scan
    __shared__ int s[1024];
    int i = blockIdx.x * 1024 + threadIdx.x;
    int v = (i < n) ? g_cnt[i] : 0;
    s[threadIdx.x] = v;
    __syncthreads();
#pragma unroll
    for (int d = 1; d < 1024; d <<= 1) {
        int t = (threadIdx.x >= d) ? s[threadIdx.x - d] : 0;
        __syncthreads();
        s[threadIdx.x] += t;
        __syncthreads();
    }
    if (i < n) g_off[i] = s[threadIdx.x] - v;  // local exclusive
    if (threadIdx.x == 1023) g_bsum[blockIdx.x] = s[1023];
}

__global__ void k_scanB(int nb) {  // serial exclusive scan of <=128 block totals
    if (threadIdx.x == 0) {
        int run = 0;
        for (int i = 0; i < nb; i++) { int t = g_bsum[i]; g_bsum[i] = run; run += t; }
    }
}

__global__ void k_scanC(int n, int e) {
    int i = blockIdx.x * blockDim.x + threadIdx.x;
    if (i < n) {
        int o = g_off[i] + g_bsum[i >> 10];
        g_off[i] = o;
        g_cur[i] = o;
    }
    if (i == 0) g_off[n] = e;
}

__global__ void k_scatter(const int* __restrict__ src, const int* __restrict__ dst, int e) {
    int i = blockIdx.x * blockDim.x + threadIdx.x;
    if (i < e) {
        int d = dst[i];
        int p = atomicAdd(&g_cur[d], 1);
        g_ssrc[p] = src[i];
    }
}

// ---------------- GEMM1: h[n,64] = x[n,128] @ W[128,64] ----------------
// 64-row tile, K chunked by 64, 256 threads, 4x4 register blocking, FFMA2 pairs.
__global__ __launch_bounds__(256) void k_gemm1(const float* __restrict__ x,
                                               const float* __restrict__ W, int n) {
    __shared__ float xs[64 * 68];
    __shared__ float ws[64 * 64];
    int tid = threadIdx.x;
    int ty = tid >> 4;
    int tx4 = (tid & 15) << 2;
    int row0 = blockIdx.x << 6;

    unsigned long long acc[4][2];
#pragma unroll
    for (int i = 0; i < 4; i++) { acc[i][0] = 0ull; acc[i][1] = 0ull; }

    for (int k0 = 0; k0 < 128; k0 += 64) {
        __syncthreads();
        for (int i = tid; i < 1024; i += 256) {
            int r = i >> 4, c = (i & 15) << 2;
            int gr = row0 + r;
            float4 v = (gr < n) ? *(const float4*)&x[gr * 128 + k0 + c]
                                : make_float4(0.f, 0.f, 0.f, 0.f);
            *(float4*)&xs[r * 68 + c] = v;
        }
        for (int i = tid; i < 1024; i += 256) {
            int k = i >> 4, c = (i & 15) << 2;
            *(float4*)&ws[k * 64 + c] = *(const float4*)&W[(k0 + k) * 64 + c];
        }
        __syncthreads();

#pragma unroll 4
        for (int k = 0; k < 64; k += 4) {
            float a[4][4];
#pragma unroll
            for (int i = 0; i < 4; i++)
                *(float4*)&a[i][0] = *(float4*)&xs[(ty * 4 + i) * 68 + k];
#pragma unroll
            for (int kk = 0; kk < 4; kk++) {
                ulonglong2 b = *(ulonglong2*)&ws[(k + kk) * 64 + tx4];
#pragma unroll
                for (int i = 0; i < 4; i++) {
                    unsigned long long av = dup2(a[i][kk]);
                    acc[i][0] = ffma2(av, b.x, acc[i][0]);
                    acc[i][1] = ffma2(av, b.y, acc[i][1]);
                }
            }
        }
    }
#pragma unroll
    for (int i = 0; i < 4; i++) {
        int gr = row0 + ty * 4 + i;
        if (gr < n) {
            ulonglong2 o; o.x = acc[i][0]; o.y = acc[i][1];
            *(ulonglong2*)&g_h[gr * 64 + tx4] = o;
        }
    }
}

// ---------------- aggregation: one warp per node, register product ----------------
__global__ void k_agg(const float* __restrict__ norm, int n) {
    int w = (blockIdx.x * blockDim.x + threadIdx.x) >> 5;
    int lane = threadIdx.x & 31;
    if (w >= n) return;
    int beg = g_off[w], end = g_off[w + 1];
    float a0 = 1.f, a1 = 1.f;
    int i = beg;
    for (; i + 4 <= end; i += 4) {  // unroll 4 edges -> MLP 8 loads
        int s0 = g_ssrc[i], s1 = g_ssrc[i + 1], s2 = g_ssrc[i + 2], s3 = g_ssrc[i + 3];
        float p0 = g_h[s0 * 64 + lane]      * g_h[s1 * 64 + lane];
        float q0 = g_h[s0 * 64 + 32 + lane] * g_h[s1 * 64 + 32 + lane];
        float p1 = g_h[s2 * 64 + lane]      * g_h[s3 * 64 + lane];
        float q1 = g_h[s2 * 64 + 32 + lane] * g_h[s3 * 64 + 32 + lane];
        a0 *= p0 * p1;
        a1 *= q0 * q1;
    }
    for (; i < end; i++) {
        int s = g_ssrc[i];
        a0 *= g_h[s * 64 + lane];
        a1 *= g_h[s * 64 + 32 + lane];
    }
    float nm = norm[w];
    g_tx[w * 64 + lane]      = a0 * nm;
    g_tx[w * 64 + 32 + lane] = a1 * nm;
}

// ---------------- GEMM2: out[n,128] = tx[n,64] @ V^T  (V is [128,64]) ----------------
// 64-row tile; output columns processed in two halves of 64 (V loaded transposed).
__global__ __launch_bounds__(256) void k_gemm2(const float* __restrict__ V,
                                               float* __restrict__ out, int n) {
    __shared__ float ts[64 * 68];
    __shared__ float vs[64 * 68];  // vs[r][j] = V[j0+j][r]
    int tid = threadIdx.x;
    int ty = tid >> 4;
    int tx4 = (tid & 15) << 2;
    int row0 = blockIdx.x << 6;

    for (int i = tid; i < 1024; i += 256) {
        int r = i >> 4, c = (i & 15) << 2;
        int gr = row0 + r;
        float4 v = (gr < n) ? *(const float4*)&g_tx[gr * 64 + c]
                            : make_float4(0.f, 0.f, 0.f, 0.f);
        *(float4*)&ts[r * 68 + c] = v;
    }

    for (int half = 0; half < 2; half++) {
        int j0 = half << 6;
        __syncthreads();  // ts ready / previous half's compute done
        for (int i = tid; i < 4096; i += 256) {
            int j = i >> 6, r = i & 63;
            vs[r * 68 + j] = V[(j0 + j) * 64 + r];
        }
        __syncthreads();

        unsigned long long acc[4][2];
#pragma unroll
        for (int i = 0; i < 4; i++) { acc[i][0] = 0ull; acc[i][1] = 0ull; }

#pragma unroll 4
        for (int k = 0; k < 64; k += 4) {
            float a[4][4];
#pragma unroll
            for (int i = 0; i < 4; i++)
                *(float4*)&a[i][0] = *(float4*)&ts[(ty * 4 + i) * 68 + k];
#pragma unroll
            for (int kk = 0; kk < 4; kk++) {
                ulonglong2 b = *(ulonglong2*)&vs[(k + kk) * 68 + tx4];
#pragma unroll
                for (int i = 0; i < 4; i++) {
                    unsigned long long av = dup2(a[i][kk]);
                    acc[i][0] = ffma2(av, b.x, acc[i][0]);
                    acc[i][1] = ffma2(av, b.y, acc[i][1]);
                }
            }
        }
#pragma unroll
        for (int i = 0; i < 4; i++) {
            int gr = row0 + ty * 4 + i;
            if (gr < n) {
                ulonglong2 o; o.x = acc[i][0]; o.y = acc[i][1];
                *(ulonglong2*)&out[gr * 128 + j0 + tx4] = o;
            }
        }
    }
}

// ---------------- launch ----------------
extern "C" void kernel_launch(void* const* d_in, const int* in_sizes, int n_in,
                              void* d_out, int out_size) {
    const float* x    = (const float*)d_in[0];
    const float* norm = (const float*)d_in[1];
    const float* W    = (const float*)d_in[2];
    const float* V    = (const float*)d_in[3];
    const int*   src  = (const int*)d_in[4];
    const int*   dst  = (const int*)d_in[5];
    float* out = (float*)d_out;

    int n = in_sizes[1];   // norm has N elements
    int e = in_sizes[4];   // src has E elements
    if (n <= 0) return;

    int nb = (n + 1023) / 1024;

    k_zero<<<(n + 255) / 256, 256>>>(n);
    k_hist<<<(e + 255) / 256, 256>>>(dst, e);
    k_scanA<<<nb, 1024>>>(n);
    k_scanB<<<1, 32>>>(nb);
    k_scanC<<<(n + 255) / 256, 256>>>(n, e);
    k_scatter<<<(e + 255) / 256, 256>>>(src, dst, e);
    k_gemm1<<<(n + 63) / 64, 256>>>(x, W, n);
    k_agg<<<(n + 7) / 8, 256>>>(norm, n);
    k_gemm2<<<(n + 63) / 64, 256>>>(V, out, n);
}

// round 4
// speedup vs baseline: 1.0063x; 1.0063x over previous
#include <cuda_runtime.h>

// Problem-fixed maxima (N=100000 nodes, E=1600000 edges, IN=128, RANK=64, HID=128)
#define MAXN 100000
#define MAXE 1600000

// ---------------- scratch (static device globals; no allocation) ----------------
// Invariant: g_cnt is all-zero at entry of every kernel_launch call:
//  - zero at module load (static init)
//  - scatter's atomicSub drains every counter back to exactly 0 each call
__device__ float g_h[MAXN * 64];      // h = x @ W
__device__ int   g_cnt[MAXN];         // in-degree histogram, then down-counting cursor
__device__ int   g_off[MAXN];         // block-local exclusive scan of counts
__device__ int   g_bsum[256];         // per-scan-block base offsets (exclusive)
__device__ int   g_ssrc[MAXE];        // src ids grouped by dst

// ---------------- packed fp32x2 helpers (Blackwell FFMA2) ----------------
__device__ __forceinline__ unsigned long long ffma2(unsigned long long a,
                                                    unsigned long long b,
                                                    unsigned long long c) {
    unsigned long long d;
    asm("fma.rn.f32x2 %0, %1, %2, %3;" : "=l"(d) : "l"(a), "l"(b), "l"(c));
    return d;
}
__device__ __forceinline__ unsigned long long dup2(float v) {
    unsigned long long r;
    asm("mov.b64 %0, {%1, %1};" : "=l"(r) : "f"(v));
    return r;
}

// ---------------- GEMM1 body: h[64 rows] = x[64,128] @ W[128,64] ----------------
__device__ __forceinline__ void gemm1_body(const float* __restrict__ x,
                                           const float* __restrict__ W,
                                           int n, int bid,
                                           float* xs, float* ws) {
    int tid = threadIdx.x;
    int ty = tid >> 4;
    int tx4 = (tid & 15) << 2;
    int row0 = bid << 6;

    unsigned long long acc[4][2];
#pragma unroll
    for (int i = 0; i < 4; i++) { acc[i][0] = 0ull; acc[i][1] = 0ull; }

    for (int k0 = 0; k0 < 128; k0 += 64) {
        __syncthreads();
        for (int i = tid; i < 1024; i += 256) {
            int r = i >> 4, c = (i & 15) << 2;
            int gr = row0 + r;
            float4 v = (gr < n) ? *(const float4*)&x[gr * 128 + k0 + c]
                                : make_float4(0.f, 0.f, 0.f, 0.f);
            *(float4*)&xs[r * 68 + c] = v;
        }
        for (int i = tid; i < 1024; i += 256) {
            int k = i >> 4, c = (i & 15) << 2;
            *(float4*)&ws[k * 64 + c] = *(const float4*)&W[(k0 + k) * 64 + c];
        }
        __syncthreads();

#pragma unroll 4
        for (int k = 0; k < 64; k += 4) {
            float a[4][4];
#pragma unroll
            for (int i = 0; i < 4; i++)
                *(float4*)&a[i][0] = *(float4*)&xs[(ty * 4 + i) * 68 + k];
#pragma unroll
            for (int kk = 0; kk < 4; kk++) {
                ulonglong2 b = *(ulonglong2*)&ws[(k + kk) * 64 + tx4];
#pragma unroll
                for (int i = 0; i < 4; i++) {
                    unsigned long long av = dup2(a[i][kk]);
                    acc[i][0] = ffma2(av, b.x, acc[i][0]);
                    acc[i][1] = ffma2(av, b.y, acc[i][1]);
                }
            }
        }
    }
#pragma unroll
    for (int i = 0; i < 4; i++) {
        int gr = row0 + ty * 4 + i;
        if (gr < n) {
            ulonglong2 o; o.x = acc[i][0]; o.y = acc[i][1];
            *(ulonglong2*)&g_h[gr * 64 + tx4] = o;
        }
    }
}

// ---------------- K1: gemm1 part A (blocks [0,gA)) + histogram ----------------
__global__ __launch_bounds__(256) void k1_gemm_hist(const float* __restrict__ x,
                                                    const float* __restrict__ W,
                                                    const int* __restrict__ dst,
                                                    int n, int e, int gA) {
    __shared__ float xs[64 * 68];
    __shared__ float ws[64 * 64];
    if ((int)blockIdx.x < gA) { gemm1_body(x, W, n, blockIdx.x, xs, ws); return; }
    int b = blockIdx.x - gA;
    int q = e >> 2;
    int i = b * 256 + threadIdx.x;
    if (i < q) {
        int4 d4 = ((const int4*)dst)[i];
        atomicAdd(&g_cnt[d4.x], 1);
        atomicAdd(&g_cnt[d4.y], 1);
        atomicAdd(&g_cnt[d4.z], 1);
        atomicAdd(&g_cnt[d4.w], 1);
    }
    if (b == 0 && threadIdx.x == 0)
        for (int j = q << 2; j < e; j++) atomicAdd(&g_cnt[dst[j]], 1);
}

// ---------------- scanA: block-local exclusive scan of g_cnt ----------------
__global__ void k_scanA(int n) {
    __shared__ int s[1024];
    int i = blockIdx.x * 1024 + threadIdx.x;
    int v = (i < n) ? g_cnt[i] : 0;
    s[threadIdx.x] = v;
    __syncthreads();
#pragma unroll
    for (int d = 1; d < 1024; d <<= 1) {
        int t = (threadIdx.x >= d) ? s[threadIdx.x - d] : 0;
        __syncthreads();
        s[threadIdx.x] += t;
        __syncthreads();
    }
    if (i < n) g_off[i] = s[threadIdx.x] - v;  // block-local exclusive
    if (threadIdx.x == 1023) g_bsum[blockIdx.x] = s[1023];
}

// ---------------- scanB: parallel exclusive scan of <=128 block totals ----------------
__global__ void k_scanB(int nb) {
    int t = threadIdx.x;        // 128 threads
    int lane = t & 31, w = t >> 5;
    int orig = (t < nb) ? g_bsum[t] : 0;
    int v = orig;
#pragma unroll
    for (int d = 1; d < 32; d <<= 1) {
        int u = __shfl_up_sync(0xffffffffu, v, d);
        if (lane >= d) v += u;
    }
    __shared__ int wsum[4];
    if (lane == 31) wsum[w] = v;
    __syncthreads();
    int add = 0;
#pragma unroll
    for (int k = 0; k < 4; k++) if (k < w) add += wsum[k];
    if (t < nb) g_bsum[t] = v - orig + add;   // exclusive prefix
}

// ---------------- scatter one edge (g_cnt doubles as down-counter) ----------------
__device__ __forceinline__ void scatter_one(int s, int d) {
    int slot = atomicSub(&g_cnt[d], 1) - 1;
    g_ssrc[g_off[d] + g_bsum[d >> 10] + slot] = s;
}

// ---------------- K3: gemm1 part B (blocks [0,gB)) + scatter ----------------
__global__ __launch_bounds__(256) void k3_gemm_scatter(const float* __restrict__ x,
                                                       const float* __restrict__ W,
                                                       const int* __restrict__ src,
                                                       const int* __restrict__ dst,
                                                       int n, int e, int gA, int gB) {
    __shared__ float xs[64 * 68];
    __shared__ float ws[64 * 64];
    if ((int)blockIdx.x < gB) { gemm1_body(x, W, n, gA + blockIdx.x, xs, ws); return; }
    int b = blockIdx.x - gB;
    int q = e >> 2;
    int i = b * 256 + threadIdx.x;
    if (i < q) {
        int4 s4 = ((const int4*)src)[i];
        int4 d4 = ((const int4*)dst)[i];
        scatter_one(s4.x, d4.x);
        scatter_one(s4.y, d4.y);
        scatter_one(s4.z, d4.z);
        scatter_one(s4.w, d4.w);
    }
    if (b == 0 && threadIdx.x == 0)
        for (int j = q << 2; j < e; j++) scatter_one(src[j], dst[j]);
}

// ---------------- K4: fused segment-product aggregation + GEMM2 ----------------
// out[64 rows, 128] = (norm * segprod) @ V^T, products built straight into smem.
__global__ __launch_bounds__(256) void k4_agg_gemm2(const float* __restrict__ norm,
                                                    const float* __restrict__ V,
                                                    float* __restrict__ out,
                                                    int n, int e) {
    __shared__ float ts[64 * 68];
    __shared__ float vs[64 * 68];  // vs[r][j] = V[j0+j][r]
    int tid = threadIdx.x;
    int lane = tid & 31, wid = tid >> 5;
    int row0 = blockIdx.x << 6;

    // --- aggregation: warp `wid` handles 8 consecutive rows ---
#pragma unroll 1
    for (int j = 0; j < 8; j++) {
        int r = wid * 8 + j;
        int v = row0 + r;
        float a0 = 0.f, a1 = 0.f;
        if (v < n) {
            a0 = 1.f; a1 = 1.f;
            int beg = g_off[v] + g_bsum[v >> 10];
            int end = (v + 1 < n) ? (g_off[v + 1] + g_bsum[(v + 1) >> 10]) : e;
            int i = beg;
            for (; i + 4 <= end; i += 4) {   // 8 outstanding 128B loads
                int s0 = g_ssrc[i], s1 = g_ssrc[i + 1];
                int s2 = g_ssrc[i + 2], s3 = g_ssrc[i + 3];
                float p0 = __ldg(&g_h[s0 * 64 + lane])      * __ldg(&g_h[s1 * 64 + lane]);
                float q0 = __ldg(&g_h[s0 * 64 + 32 + lane]) * __ldg(&g_h[s1 * 64 + 32 + lane]);
                float p1 = __ldg(&g_h[s2 * 64 + lane])      * __ldg(&g_h[s3 * 64 + lane]);
                float q1 = __ldg(&g_h[s2 * 64 + 32 + lane]) * __ldg(&g_h[s3 * 64 + 32 + lane]);
                a0 *= p0 * p1;
                a1 *= q0 * q1;
            }
            for (; i < end; i++) {
                int s = g_ssrc[i];
                a0 *= __ldg(&g_h[s * 64 + lane]);
                a1 *= __ldg(&g_h[s * 64 + 32 + lane]);
            }
            float nm = __ldg(&norm[v]);
            a0 *= nm; a1 *= nm;
        }
        ts[r * 68 + lane]      = a0;
        ts[r * 68 + 32 + lane] = a1;
    }

    // --- GEMM2: out = ts @ V^T, two 64-col halves ---
    int ty = tid >> 4;
    int tx4 = (tid & 15) << 2;
    for (int half = 0; half < 2; half++) {
        int j0 = half << 6;
        __syncthreads();   // ts ready / previous half's compute done
        for (int i = tid; i < 4096; i += 256) {
            int j = i >> 6, r = i & 63;
            vs[r * 68 + j] = V[(j0 + j) * 64 + r];
        }
        __syncthreads();

        unsigned long long acc[4][2];
#pragma unroll
        for (int i = 0; i < 4; i++) { acc[i][0] = 0ull; acc[i][1] = 0ull; }

#pragma unroll 4
        for (int k = 0; k < 64; k += 4) {
            float a[4][4];
#pragma unroll
            for (int i = 0; i < 4; i++)
                *(float4*)&a[i][0] = *(float4*)&ts[(ty * 4 + i) * 68 + k];
#pragma unroll
            for (int kk = 0; kk < 4; kk++) {
                ulonglong2 b = *(ulonglong2*)&vs[(k + kk) * 68 + tx4];
#pragma unroll
                for (int i = 0; i < 4; i++) {
                    unsigned long long av = dup2(a[i][kk]);
                    acc[i][0] = ffma2(av, b.x, acc[i][0]);
                    acc[i][1] = ffma2(av, b.y, acc[i][1]);
                }
            }
        }
#pragma unroll
        for (int i = 0; i < 4; i++) {
            int gr = row0 + ty * 4 + i;
            if (gr < n) {
                ulonglong2 o; o.x = acc[i][0]; o.y = acc[i][1];
                *(ulonglong2*)&out[gr * 128 + j0 + tx4] = o;
            }
        }
    }
}

// ---------------- launch ----------------
extern "C" void kernel_launch(void* const* d_in, const int* in_sizes, int n_in,
                              void* d_out, int out_size) {
    const float* x    = (const float*)d_in[0];
    const float* norm = (const float*)d_in[1];
    const float* W    = (const float*)d_in[2];
    const float* V    = (const float*)d_in[3];
    const int*   src  = (const int*)d_in[4];
    const int*   dst  = (const int*)d_in[5];
    float* out = (float*)d_out;

    int n = in_sizes[1];   // norm has N elements
    int e = in_sizes[4];   // src has E elements
    if (n <= 0) return;

    int G1 = (n + 63) / 64;          // gemm1 blocks total
    int gA = G1 / 3;                 // overlapped with histogram
    int gB = G1 - gA;                // overlapped with scatter
    int q  = e >> 2;
    int eb = (q + 255) / 256;        // edge blocks (4 edges/thread)
    if (eb < 1) eb = 1;
    int nb = (n + 1023) / 1024;      // scan blocks (<=128 required by scanB)

    k1_gemm_hist<<<gA + eb, 256>>>(x, W, dst, n, e, gA);
    k_scanA<<<nb, 1024>>>(n);
    k_scanB<<<1, 128>>>(nb);
    k3_gemm_scatter<<<gB + eb, 256>>>(x, W, src, dst, n, e, gA, gB);
    k4_agg_gemm2<<<G1, 256>>>(norm, V, out, n, e);
}